// round 1
// baseline (speedup 1.0000x reference)
#include <cuda_runtime.h>

#define E_ 28
#define H_ 4
#define HD_ 7
#define FF_ 256
#define LMAX_ 8
#define T_ 512
#define B_ 64
#define S_ 4096
#define NSPANS (B_ * T_)

// ---- shared memory layout (floats) ----
#define OFF_WQKV 0          // 84*28 = 2352
#define OFF_BQKV 2352       // 84
#define OFF_WO   2436       // 28*28 = 784
#define OFF_BO   3220       // 28
#define OFF_G1   3248       // 28
#define OFF_B1L  3276       // 28
#define OFF_W1   3304       // 256*28 = 7168
#define OFF_B1   10472      // 256
#define OFF_W2   10728      // 28*256 = 7168
#define OFF_B2   17896      // 28
#define OFF_G2   17924      // 28
#define OFF_B2L  17952      // 28
#define OFF_PAD  17980      // 28
#define OFF_SCR  18008
#define SCR_PER_WARP 672    // A[224] | Kb[224] | Vb[224]
#define SMEM_FLOATS (OFF_SCR + 8 * SCR_PER_WARP)   // 23384
#define SMEM_BYTES  (SMEM_FLOATS * 4)              // 93536

__device__ __forceinline__ void cp_f4(float* dst, const float* src, int nfloats) {
    const int n4 = nfloats >> 2;
    for (int i = threadIdx.x; i < n4; i += blockDim.x)
        reinterpret_cast<float4*>(dst)[i] = reinterpret_cast<const float4*>(src)[i];
}

// dot of 28-elem register vector x with 28-elem smem row w (float4-vectorized weight loads)
__device__ __forceinline__ float dot28r(const float* x, const float* w) {
    const float4* w4 = reinterpret_cast<const float4*>(w);
    float acc = 0.0f;
#pragma unroll
    for (int j = 0; j < 7; j++) {
        float4 b = w4[j];
        acc = fmaf(x[4 * j + 0], b.x, acc);
        acc = fmaf(x[4 * j + 1], b.y, acc);
        acc = fmaf(x[4 * j + 2], b.z, acc);
        acc = fmaf(x[4 * j + 3], b.w, acc);
    }
    return acc;
}

__global__ __launch_bounds__(256, 2)
void span_transformer_kernel(
    const float* __restrict__ emb,
    const int*   __restrict__ span_lengths,
    const int*   __restrict__ num_spans,
    const float* __restrict__ in_proj_w, const float* __restrict__ in_proj_b,
    const float* __restrict__ out_proj_w, const float* __restrict__ out_proj_b,
    const float* __restrict__ ln1_g, const float* __restrict__ ln1_b,
    const float* __restrict__ lin1_w, const float* __restrict__ lin1_b,
    const float* __restrict__ lin2_w, const float* __restrict__ lin2_b,
    const float* __restrict__ ln2_g, const float* __restrict__ ln2_b,
    const float* __restrict__ pad_token,
    float* __restrict__ outp)
{
    extern __shared__ float sm[];

    // ---- cooperative weight staging ----
    cp_f4(sm + OFF_WQKV, in_proj_w, 2352);
    cp_f4(sm + OFF_BQKV, in_proj_b, 84);
    cp_f4(sm + OFF_WO,   out_proj_w, 784);
    cp_f4(sm + OFF_BO,   out_proj_b, 28);
    cp_f4(sm + OFF_G1,   ln1_g, 28);
    cp_f4(sm + OFF_B1L,  ln1_b, 28);
    cp_f4(sm + OFF_W1,   lin1_w, 7168);
    cp_f4(sm + OFF_B1,   lin1_b, 256);
    cp_f4(sm + OFF_W2,   lin2_w, 7168);
    cp_f4(sm + OFF_B2,   lin2_b, 28);
    cp_f4(sm + OFF_G2,   ln2_g, 28);
    cp_f4(sm + OFF_B2L,  ln2_b, 28);
    cp_f4(sm + OFF_PAD,  pad_token, 28);
    __syncthreads();

    const int warp = threadIdx.x >> 5;
    const int lane = threadIdx.x & 31;
    const int l = lane & 7;      // token within span
    const int h = lane >> 3;     // head / E-slice index
    const int e0 = h * 7;        // start of this thread's E-slice

    float* A  = sm + OFF_SCR + warp * SCR_PER_WARP;  // x row-major [8][28] (then xn)
    float* Kb = A + 224;                             // k [8][28] (then ao)
    float* Vb = A + 448;                             // v [8][28]

    const int warps_total = gridDim.x * 8;
    for (int span = blockIdx.x * 8 + warp; span < NSPANS; span += warps_total) {
        const int b = span >> 9;
        const int t = span & (T_ - 1);

        // ---- load x: span covers 224 contiguous floats of emb ----
        {
            const float4* src = reinterpret_cast<const float4*>(emb + b * (S_ * E_) + t * 224);
            float4* A4 = reinterpret_cast<float4*>(A);
            A4[lane] = src[lane];
            if (lane < 24) A4[lane + 32] = src[lane + 32];
        }
        __syncwarp();

        // ---- QKV projection (each thread: its head-slice of q,k,v for its token) ----
        float xr[28];
        {
            const float4* r4 = reinterpret_cast<const float4*>(A + l * 28);
#pragma unroll
            for (int j = 0; j < 7; j++) {
                float4 v = r4[j];
                xr[4 * j] = v.x; xr[4 * j + 1] = v.y; xr[4 * j + 2] = v.z; xr[4 * j + 3] = v.w;
            }
        }
        float q[7];
#pragma unroll
        for (int d = 0; d < 7; d++) {
            const int rq = e0 + d;
            q[d]        = sm[OFF_BQKV + rq]      + dot28r(xr, sm + OFF_WQKV + rq * 28);
            float kk    = sm[OFF_BQKV + 28 + rq] + dot28r(xr, sm + OFF_WQKV + (28 + rq) * 28);
            float vv    = sm[OFF_BQKV + 56 + rq] + dot28r(xr, sm + OFF_WQKV + (56 + rq) * 28);
            Kb[l * 28 + rq] = kk;
            Vb[l * 28 + rq] = vv;
        }
        __syncwarp();

        // ---- attention within span (8x8, per head = per thread slice) ----
        const int len = span_lengths[b * T_ + t];
        float s[8];
#pragma unroll
        for (int kk = 0; kk < 8; kk++) {
            const float* kr = Kb + kk * 28 + e0;
            float acc = 0.0f;
#pragma unroll
            for (int d = 0; d < 7; d++) acc = fmaf(q[d], kr[d], acc);
            s[kk] = (kk < len) ? acc * 0.3779644730092272f : -1e9f;
        }
        float mx = s[0];
#pragma unroll
        for (int kk = 1; kk < 8; kk++) mx = fmaxf(mx, s[kk]);
        float p[8], psum = 0.0f;
#pragma unroll
        for (int kk = 0; kk < 8; kk++) { p[kk] = expf(s[kk] - mx); psum += p[kk]; }
        const float pinv = 1.0f / psum;

        float ao[7];
#pragma unroll
        for (int d = 0; d < 7; d++) {
            float acc = 0.0f;
#pragma unroll
            for (int kk = 0; kk < 8; kk++) acc = fmaf(p[kk], Vb[kk * 28 + e0 + d], acc);
            ao[d] = acc * pinv;
        }
        __syncwarp();   // all score/AV reads of Kb done before overwrite
#pragma unroll
        for (int d = 0; d < 7; d++) Kb[l * 28 + e0 + d] = ao[d];
        __syncwarp();

        // ---- out projection + residual + LN1 ----
        float aor[28];
        {
            const float4* r4 = reinterpret_cast<const float4*>(Kb + l * 28);
#pragma unroll
            for (int j = 0; j < 7; j++) {
                float4 v = r4[j];
                aor[4 * j] = v.x; aor[4 * j + 1] = v.y; aor[4 * j + 2] = v.z; aor[4 * j + 3] = v.w;
            }
        }
        float y[7];
#pragma unroll
        for (int d = 0; d < 7; d++) {
            const int ep = e0 + d;
            float o = sm[OFF_BO + ep] + dot28r(aor, sm + OFF_WO + ep * 28);
            y[d] = A[l * 28 + ep] + o;
        }
        float s1 = 0.0f;
#pragma unroll
        for (int d = 0; d < 7; d++) s1 += y[d];
        s1 += __shfl_xor_sync(0xffffffffu, s1, 8);
        s1 += __shfl_xor_sync(0xffffffffu, s1, 16);
        const float mu1 = s1 * (1.0f / 28.0f);
        float s2 = 0.0f;
#pragma unroll
        for (int d = 0; d < 7; d++) { float dd = y[d] - mu1; s2 += dd * dd; }
        s2 += __shfl_xor_sync(0xffffffffu, s2, 8);
        s2 += __shfl_xor_sync(0xffffffffu, s2, 16);
        const float rs1 = rsqrtf(s2 * (1.0f / 28.0f) + 1e-5f);
#pragma unroll
        for (int d = 0; d < 7; d++) {
            const int ep = e0 + d;
            A[l * 28 + ep] = (y[d] - mu1) * rs1 * sm[OFF_G1 + ep] + sm[OFF_B1L + ep];
        }
        __syncwarp();

        // ---- FFN fused: each thread handles f = 4i+h, rank-1 update into ff[28] ----
        float xnf[28];
        {
            const float4* r4 = reinterpret_cast<const float4*>(A + l * 28);
#pragma unroll
            for (int j = 0; j < 7; j++) {
                float4 v = r4[j];
                xnf[4 * j] = v.x; xnf[4 * j + 1] = v.y; xnf[4 * j + 2] = v.z; xnf[4 * j + 3] = v.w;
            }
        }
        float ff[28];
#pragma unroll
        for (int ep = 0; ep < 28; ep++) ff[ep] = 0.0f;
#pragma unroll 2
        for (int i = 0; i < 64; i++) {
            const int f = 4 * i + h;
            float a1 = sm[OFF_B1 + f] + dot28r(xnf, sm + OFF_W1 + f * 28);
            a1 = fmaxf(a1, 0.0f);
            const float* w2c = sm + OFF_W2 + f;
#pragma unroll
            for (int ep = 0; ep < 28; ep++) ff[ep] = fmaf(a1, w2c[ep * 256], ff[ep]);
        }
#pragma unroll
        for (int ep = 0; ep < 28; ep++) {
            float v = ff[ep];
            v += __shfl_xor_sync(0xffffffffu, v, 8);
            v += __shfl_xor_sync(0xffffffffu, v, 16);
            ff[ep] = v + sm[OFF_B2 + ep];
        }

        // ---- residual2 + LN2 (full row per thread, no reduction needed) ----
        float y2[28], mu2 = 0.0f;
#pragma unroll
        for (int ep = 0; ep < 28; ep++) { y2[ep] = xnf[ep] + ff[ep]; mu2 += y2[ep]; }
        mu2 *= (1.0f / 28.0f);
        float v2 = 0.0f;
#pragma unroll
        for (int ep = 0; ep < 28; ep++) { float dd = y2[ep] - mu2; v2 += dd * dd; }
        const float rs2 = rsqrtf(v2 * (1.0f / 28.0f) + 1e-5f);

        // ---- masked mean-pool over tokens (reduce over l via shfl) ----
        const bool act = (l < len);
        float po[28];
#pragma unroll
        for (int ep = 0; ep < 28; ep++) {
            float x2 = (y2[ep] - mu2) * rs2 * sm[OFF_G2 + ep] + sm[OFF_B2L + ep];
            po[ep] = act ? x2 : 0.0f;
        }
#pragma unroll
        for (int ep = 0; ep < 28; ep++) {
            float v = po[ep];
            v += __shfl_xor_sync(0xffffffffu, v, 1);
            v += __shfl_xor_sync(0xffffffffu, v, 2);
            v += __shfl_xor_sync(0xffffffffu, v, 4);
            po[ep] = v;
        }
        const float invlen = 1.0f / (float)len;

        // ---- output: pooled (valid) or pad_token ----
        const int ns = num_spans[b];
        float* orow = outp + span * 28;
        if (t < ns) {
            if (lane == 0) {
                float4* A4 = reinterpret_cast<float4*>(A);
#pragma unroll
                for (int j = 0; j < 7; j++) {
                    float4 v;
                    v.x = po[4 * j] * invlen;
                    v.y = po[4 * j + 1] * invlen;
                    v.z = po[4 * j + 2] * invlen;
                    v.w = po[4 * j + 3] * invlen;
                    A4[j] = v;
                }
            }
            __syncwarp();
            if (lane < 7)
                reinterpret_cast<float4*>(orow)[lane] = reinterpret_cast<float4*>(A)[lane];
        } else {
            if (lane < 7)
                reinterpret_cast<float4*>(orow)[lane] =
                    reinterpret_cast<const float4*>(sm + OFF_PAD)[lane];
        }
        __syncwarp();   // A reused next iteration
    }
}

extern "C" void kernel_launch(void* const* d_in, const int* in_sizes, int n_in,
                              void* d_out, int out_size) {
    const float* emb          = (const float*)d_in[0];
    const int*   span_lengths = (const int*)  d_in[1];
    const int*   num_spans    = (const int*)  d_in[2];
    const float* in_proj_w    = (const float*)d_in[3];
    const float* in_proj_b    = (const float*)d_in[4];
    const float* out_proj_w   = (const float*)d_in[5];
    const float* out_proj_b   = (const float*)d_in[6];
    const float* ln1_g        = (const float*)d_in[7];
    const float* ln1_b        = (const float*)d_in[8];
    const float* lin1_w       = (const float*)d_in[9];
    const float* lin1_b       = (const float*)d_in[10];
    const float* lin2_w       = (const float*)d_in[11];
    const float* lin2_b       = (const float*)d_in[12];
    const float* ln2_g        = (const float*)d_in[13];
    const float* ln2_b        = (const float*)d_in[14];
    const float* pad_token    = (const float*)d_in[15];
    float* outp = (float*)d_out;

    cudaFuncSetAttribute(span_transformer_kernel,
                         cudaFuncAttributeMaxDynamicSharedMemorySize, SMEM_BYTES);

    span_transformer_kernel<<<296, 256, SMEM_BYTES>>>(
        emb, span_lengths, num_spans,
        in_proj_w, in_proj_b, out_proj_w, out_proj_b,
        ln1_g, ln1_b, lin1_w, lin1_b, lin2_w, lin2_b,
        ln2_g, ln2_b, pad_token, outp);
}

// round 2
// speedup vs baseline: 1.2384x; 1.2384x over previous
#include <cuda_runtime.h>

#define E_ 28
#define H_ 4
#define HD_ 7
#define FF_ 256
#define LMAX_ 8
#define T_ 512
#define B_ 64
#define S_ 4096
#define NSPANS (B_ * T_)

// ---- shared memory layout (floats) ----
#define OFF_WQKV 0          // 84*28 = 2352
#define OFF_BQKV 2352       // 84
#define OFF_WO   2436       // 28*28 = 784
#define OFF_BO   3220       // 28
#define OFF_G1   3248       // 28
#define OFF_B1L  3276       // 28
#define OFF_W1   3304       // 256*28 = 7168
#define OFF_B1   10472      // 256
#define OFF_W2T  10728      // 256*28 = 7168  (TRANSPOSED: row f = 28 contiguous floats)
#define OFF_B2   17896      // 28
#define OFF_G2   17924      // 28
#define OFF_B2L  17952      // 28
#define OFF_PAD  17980      // 28
#define OFF_SCR  18008
#define SCR_PER_WARP 672    // A[224] | Kb[224] | Vb[224]
#define SMEM_FLOATS (OFF_SCR + 8 * SCR_PER_WARP)   // 23384
#define SMEM_BYTES  (SMEM_FLOATS * 4)              // 93536

__device__ __forceinline__ void cp_f4(float* dst, const float* src, int nfloats) {
    const int n4 = nfloats >> 2;
    for (int i = threadIdx.x; i < n4; i += blockDim.x)
        reinterpret_cast<float4*>(dst)[i] = reinterpret_cast<const float4*>(src)[i];
}

// dot of 28-elem register vector x with 28-elem smem row w (float4-vectorized weight loads)
__device__ __forceinline__ float dot28r(const float* x, const float* w) {
    const float4* w4 = reinterpret_cast<const float4*>(w);
    float acc = 0.0f;
#pragma unroll
    for (int j = 0; j < 7; j++) {
        float4 b = w4[j];
        acc = fmaf(x[4 * j + 0], b.x, acc);
        acc = fmaf(x[4 * j + 1], b.y, acc);
        acc = fmaf(x[4 * j + 2], b.z, acc);
        acc = fmaf(x[4 * j + 3], b.w, acc);
    }
    return acc;
}

__global__ __launch_bounds__(256, 2)
void span_transformer_kernel(
    const float* __restrict__ emb,
    const int*   __restrict__ span_lengths,
    const int*   __restrict__ num_spans,
    const float* __restrict__ in_proj_w, const float* __restrict__ in_proj_b,
    const float* __restrict__ out_proj_w, const float* __restrict__ out_proj_b,
    const float* __restrict__ ln1_g, const float* __restrict__ ln1_b,
    const float* __restrict__ lin1_w, const float* __restrict__ lin1_b,
    const float* __restrict__ lin2_w, const float* __restrict__ lin2_b,
    const float* __restrict__ ln2_g, const float* __restrict__ ln2_b,
    const float* __restrict__ pad_token,
    float* __restrict__ outp)
{
    extern __shared__ float sm[];

    // ---- cooperative weight staging ----
    cp_f4(sm + OFF_WQKV, in_proj_w, 2352);
    cp_f4(sm + OFF_BQKV, in_proj_b, 84);
    cp_f4(sm + OFF_WO,   out_proj_w, 784);
    cp_f4(sm + OFF_BO,   out_proj_b, 28);
    cp_f4(sm + OFF_G1,   ln1_g, 28);
    cp_f4(sm + OFF_B1L,  ln1_b, 28);
    cp_f4(sm + OFF_W1,   lin1_w, 7168);
    cp_f4(sm + OFF_B1,   lin1_b, 256);
    // lin2_w is [28][256]; stage TRANSPOSED so column f becomes a contiguous
    // 28-float (112B, 16B-aligned) row -> 7 LDS.128 instead of 28 strided LDS.32.
    for (int i = threadIdx.x; i < 7168; i += blockDim.x) {
        int e = i >> 8;        // source row    (0..27)
        int f = i & 255;       // source column (0..255)
        sm[OFF_W2T + f * 28 + e] = lin2_w[i];
    }
    cp_f4(sm + OFF_B2,   lin2_b, 28);
    cp_f4(sm + OFF_G2,   ln2_g, 28);
    cp_f4(sm + OFF_B2L,  ln2_b, 28);
    cp_f4(sm + OFF_PAD,  pad_token, 28);
    __syncthreads();

    const int warp = threadIdx.x >> 5;
    const int lane = threadIdx.x & 31;
    const int l = lane & 7;      // token within span
    const int h = lane >> 3;     // head / E-slice index
    const int e0 = h * 7;        // start of this thread's E-slice

    float* A  = sm + OFF_SCR + warp * SCR_PER_WARP;  // x row-major [8][28] (then xn)
    float* Kb = A + 224;                             // k [8][28] (then ao)
    float* Vb = A + 448;                             // v [8][28]

    const int warps_total = gridDim.x * 8;
    for (int span = blockIdx.x * 8 + warp; span < NSPANS; span += warps_total) {
        const int b = span >> 9;
        const int t = span & (T_ - 1);

        // ---- load x: span covers 224 contiguous floats of emb ----
        {
            const float4* src = reinterpret_cast<const float4*>(emb + b * (S_ * E_) + t * 224);
            float4* A4 = reinterpret_cast<float4*>(A);
            A4[lane] = src[lane];
            if (lane < 24) A4[lane + 32] = src[lane + 32];
        }
        __syncwarp();

        // ---- QKV projection (each thread: its head-slice of q,k,v for its token) ----
        float xr[28];
        {
            const float4* r4 = reinterpret_cast<const float4*>(A + l * 28);
#pragma unroll
            for (int j = 0; j < 7; j++) {
                float4 v = r4[j];
                xr[4 * j] = v.x; xr[4 * j + 1] = v.y; xr[4 * j + 2] = v.z; xr[4 * j + 3] = v.w;
            }
        }
        float q[7];
#pragma unroll
        for (int d = 0; d < 7; d++) {
            const int rq = e0 + d;
            q[d]        = sm[OFF_BQKV + rq]      + dot28r(xr, sm + OFF_WQKV + rq * 28);
            float kk    = sm[OFF_BQKV + 28 + rq] + dot28r(xr, sm + OFF_WQKV + (28 + rq) * 28);
            float vv    = sm[OFF_BQKV + 56 + rq] + dot28r(xr, sm + OFF_WQKV + (56 + rq) * 28);
            Kb[l * 28 + rq] = kk;
            Vb[l * 28 + rq] = vv;
        }
        __syncwarp();

        // ---- attention within span (8x8, per head = per thread slice) ----
        const int len = span_lengths[b * T_ + t];
        float s[8];
#pragma unroll
        for (int kk = 0; kk < 8; kk++) {
            const float* kr = Kb + kk * 28 + e0;
            float acc = 0.0f;
#pragma unroll
            for (int d = 0; d < 7; d++) acc = fmaf(q[d], kr[d], acc);
            s[kk] = (kk < len) ? acc * 0.3779644730092272f : -1e9f;
        }
        float mx = s[0];
#pragma unroll
        for (int kk = 1; kk < 8; kk++) mx = fmaxf(mx, s[kk]);
        float p[8], psum = 0.0f;
#pragma unroll
        for (int kk = 0; kk < 8; kk++) { p[kk] = expf(s[kk] - mx); psum += p[kk]; }
        const float pinv = 1.0f / psum;

        float ao[7];
#pragma unroll
        for (int d = 0; d < 7; d++) {
            float acc = 0.0f;
#pragma unroll
            for (int kk = 0; kk < 8; kk++) acc = fmaf(p[kk], Vb[kk * 28 + e0 + d], acc);
            ao[d] = acc * pinv;
        }
        __syncwarp();   // all score/AV reads of Kb done before overwrite
#pragma unroll
        for (int d = 0; d < 7; d++) Kb[l * 28 + e0 + d] = ao[d];
        __syncwarp();

        // ---- out projection + residual + LN1 ----
        float aor[28];
        {
            const float4* r4 = reinterpret_cast<const float4*>(Kb + l * 28);
#pragma unroll
            for (int j = 0; j < 7; j++) {
                float4 v = r4[j];
                aor[4 * j] = v.x; aor[4 * j + 1] = v.y; aor[4 * j + 2] = v.z; aor[4 * j + 3] = v.w;
            }
        }
        float y[7];
#pragma unroll
        for (int d = 0; d < 7; d++) {
            const int ep = e0 + d;
            float o = sm[OFF_BO + ep] + dot28r(aor, sm + OFF_WO + ep * 28);
            y[d] = A[l * 28 + ep] + o;
        }
        float s1 = 0.0f;
#pragma unroll
        for (int d = 0; d < 7; d++) s1 += y[d];
        s1 += __shfl_xor_sync(0xffffffffu, s1, 8);
        s1 += __shfl_xor_sync(0xffffffffu, s1, 16);
        const float mu1 = s1 * (1.0f / 28.0f);
        float s2 = 0.0f;
#pragma unroll
        for (int d = 0; d < 7; d++) { float dd = y[d] - mu1; s2 += dd * dd; }
        s2 += __shfl_xor_sync(0xffffffffu, s2, 8);
        s2 += __shfl_xor_sync(0xffffffffu, s2, 16);
        const float rs1 = rsqrtf(s2 * (1.0f / 28.0f) + 1e-5f);
#pragma unroll
        for (int d = 0; d < 7; d++) {
            const int ep = e0 + d;
            A[l * 28 + ep] = (y[d] - mu1) * rs1 * sm[OFF_G1 + ep] + sm[OFF_B1L + ep];
        }
        __syncwarp();

        // ---- FFN fused: each thread handles f = 4i+h, rank-1 update into ff[28] ----
        float xnf[28];
        {
            const float4* r4 = reinterpret_cast<const float4*>(A + l * 28);
#pragma unroll
            for (int j = 0; j < 7; j++) {
                float4 v = r4[j];
                xnf[4 * j] = v.x; xnf[4 * j + 1] = v.y; xnf[4 * j + 2] = v.z; xnf[4 * j + 3] = v.w;
            }
        }
        float ff[28];
#pragma unroll
        for (int ep = 0; ep < 28; ep++) ff[ep] = 0.0f;
#pragma unroll 2
        for (int i = 0; i < 64; i++) {
            const int f = 4 * i + h;
            float a1 = sm[OFF_B1 + f] + dot28r(xnf, sm + OFF_W1 + f * 28);
            a1 = fmaxf(a1, 0.0f);
            const float4* w2r = reinterpret_cast<const float4*>(sm + OFF_W2T + f * 28);
#pragma unroll
            for (int j = 0; j < 7; j++) {
                float4 w = w2r[j];
                ff[4 * j + 0] = fmaf(a1, w.x, ff[4 * j + 0]);
                ff[4 * j + 1] = fmaf(a1, w.y, ff[4 * j + 1]);
                ff[4 * j + 2] = fmaf(a1, w.z, ff[4 * j + 2]);
                ff[4 * j + 3] = fmaf(a1, w.w, ff[4 * j + 3]);
            }
        }
#pragma unroll
        for (int ep = 0; ep < 28; ep++) {
            float v = ff[ep];
            v += __shfl_xor_sync(0xffffffffu, v, 8);
            v += __shfl_xor_sync(0xffffffffu, v, 16);
            ff[ep] = v + sm[OFF_B2 + ep];
        }

        // ---- residual2 + LN2 (full row per thread, no reduction needed) ----
        float y2[28], mu2 = 0.0f;
#pragma unroll
        for (int ep = 0; ep < 28; ep++) { y2[ep] = xnf[ep] + ff[ep]; mu2 += y2[ep]; }
        mu2 *= (1.0f / 28.0f);
        float v2 = 0.0f;
#pragma unroll
        for (int ep = 0; ep < 28; ep++) { float dd = y2[ep] - mu2; v2 += dd * dd; }
        const float rs2 = rsqrtf(v2 * (1.0f / 28.0f) + 1e-5f);

        // ---- masked mean-pool over tokens (reduce over l via shfl) ----
        const bool act = (l < len);
        float po[28];
#pragma unroll
        for (int ep = 0; ep < 28; ep++) {
            float x2 = (y2[ep] - mu2) * rs2 * sm[OFF_G2 + ep] + sm[OFF_B2L + ep];
            po[ep] = act ? x2 : 0.0f;
        }
#pragma unroll
        for (int ep = 0; ep < 28; ep++) {
            float v = po[ep];
            v += __shfl_xor_sync(0xffffffffu, v, 1);
            v += __shfl_xor_sync(0xffffffffu, v, 2);
            v += __shfl_xor_sync(0xffffffffu, v, 4);
            po[ep] = v;
        }
        const float invlen = 1.0f / (float)len;

        // ---- output: pooled (valid) or pad_token ----
        const int ns = num_spans[b];
        float* orow = outp + span * 28;
        if (t < ns) {
            if (lane == 0) {
                float4* A4 = reinterpret_cast<float4*>(A);
#pragma unroll
                for (int j = 0; j < 7; j++) {
                    float4 v;
                    v.x = po[4 * j] * invlen;
                    v.y = po[4 * j + 1] * invlen;
                    v.z = po[4 * j + 2] * invlen;
                    v.w = po[4 * j + 3] * invlen;
                    A4[j] = v;
                }
            }
            __syncwarp();
            if (lane < 7)
                reinterpret_cast<float4*>(orow)[lane] = reinterpret_cast<float4*>(A)[lane];
        } else {
            if (lane < 7)
                reinterpret_cast<float4*>(orow)[lane] =
                    reinterpret_cast<const float4*>(sm + OFF_PAD)[lane];
        }
        __syncwarp();   // A reused next iteration
    }
}

extern "C" void kernel_launch(void* const* d_in, const int* in_sizes, int n_in,
                              void* d_out, int out_size) {
    const float* emb          = (const float*)d_in[0];
    const int*   span_lengths = (const int*)  d_in[1];
    const int*   num_spans    = (const int*)  d_in[2];
    const float* in_proj_w    = (const float*)d_in[3];
    const float* in_proj_b    = (const float*)d_in[4];
    const float* out_proj_w   = (const float*)d_in[5];
    const float* out_proj_b   = (const float*)d_in[6];
    const float* ln1_g        = (const float*)d_in[7];
    const float* ln1_b        = (const float*)d_in[8];
    const float* lin1_w       = (const float*)d_in[9];
    const float* lin1_b       = (const float*)d_in[10];
    const float* lin2_w       = (const float*)d_in[11];
    const float* lin2_b       = (const float*)d_in[12];
    const float* ln2_g        = (const float*)d_in[13];
    const float* ln2_b        = (const float*)d_in[14];
    const float* pad_token    = (const float*)d_in[15];
    float* outp = (float*)d_out;

    cudaFuncSetAttribute(span_transformer_kernel,
                         cudaFuncAttributeMaxDynamicSharedMemorySize, SMEM_BYTES);

    span_transformer_kernel<<<296, 256, SMEM_BYTES>>>(
        emb, span_lengths, num_spans,
        in_proj_w, in_proj_b, out_proj_w, out_proj_b,
        ln1_g, ln1_b, lin1_w, lin1_b, lin2_w, lin2_b,
        ln2_g, ln2_b, pad_token, outp);
}